// round 1
// baseline (speedup 1.0000x reference)
#include <cuda_runtime.h>

#define T_STEPS 200
#define NIN     5
#define H       32
#define WARPS_PER_BLOCK 4

// ---- f32x2 packed helpers (sm_103a) ----
__device__ __forceinline__ unsigned long long pack2(float lo, float hi) {
    unsigned long long r;
    asm("mov.b64 %0, {%1, %2};" : "=l"(r) : "f"(lo), "f"(hi));
    return r;
}
__device__ __forceinline__ void unpack2(unsigned long long v, float& lo, float& hi) {
    asm("mov.b64 {%0, %1}, %2;" : "=f"(lo), "=f"(hi) : "l"(v));
}
__device__ __forceinline__ unsigned long long ffma2(unsigned long long a,
                                                    unsigned long long b,
                                                    unsigned long long c) {
    unsigned long long d;
    asm("fma.rn.f32x2 %0, %1, %2, %3;" : "=l"(d) : "l"(a), "l"(b), "l"(c));
    return d;
}

__device__ __forceinline__ float sigf(float x) {
    // sigmoid via EX2-approx + RCP-approx (MUFU). ~2 ulp, fine for 1e-3.
    return __fdividef(1.0f, 1.0f + __expf(-x));
}
__device__ __forceinline__ float tanh_f(float x) {
    return fmaf(2.0f, sigf(2.0f * x), -1.0f);
}

__global__ void __launch_bounds__(WARPS_PER_BLOCK * 32)
lstm_kernel(const float* __restrict__ x,
            const float* __restrict__ W_ih,
            const float* __restrict__ W_hh,
            const float* __restrict__ b_ih,
            const float* __restrict__ b_hh,
            const float* __restrict__ W_fc,
            const float* __restrict__ b_fc,
            float* __restrict__ out,
            int B) {
    __shared__ float4 x4_sh[WARPS_PER_BLOCK][ (T_STEPS * NIN) / 4 ];  // 250 float4 per warp
    __shared__ __align__(16) float h_sh[WARPS_PER_BLOCK][2][H];

    const int lane = threadIdx.x & 31;
    const int w    = threadIdx.x >> 5;
    const int b    = blockIdx.x * WARPS_PER_BLOCK + w;
    if (b >= B) return;

    // ---- load recurrent weights into registers, packed over K ----
    const int row_i = lane;
    const int row_f = H + lane;
    const int row_g = 2 * H + lane;
    const int row_o = 3 * H + lane;

    unsigned long long whh_i[H / 2], whh_f[H / 2], whh_g[H / 2], whh_o[H / 2];
    {
        const float2* Wi = (const float2*)(W_hh + row_i * H);
        const float2* Wf = (const float2*)(W_hh + row_f * H);
        const float2* Wg = (const float2*)(W_hh + row_g * H);
        const float2* Wo = (const float2*)(W_hh + row_o * H);
#pragma unroll
        for (int k = 0; k < H / 2; ++k) {
            float2 vi = Wi[k], vf = Wf[k], vg = Wg[k], vo = Wo[k];
            whh_i[k] = pack2(vi.x, vi.y);
            whh_f[k] = pack2(vf.x, vf.y);
            whh_g[k] = pack2(vg.x, vg.y);
            whh_o[k] = pack2(vo.x, vo.y);
        }
    }

    // input-projection weights, gate pairs (i,f) and (g,o)
    unsigned long long wih_if[NIN], wih_go[NIN];
#pragma unroll
    for (int m = 0; m < NIN; ++m) {
        wih_if[m] = pack2(W_ih[row_i * NIN + m], W_ih[row_f * NIN + m]);
        wih_go[m] = pack2(W_ih[row_g * NIN + m], W_ih[row_o * NIN + m]);
    }
    const unsigned long long bias_if =
        pack2(b_ih[row_i] + b_hh[row_i], b_ih[row_f] + b_hh[row_f]);
    const unsigned long long bias_go =
        pack2(b_ih[row_g] + b_hh[row_g], b_ih[row_o] + b_hh[row_o]);

    // ---- stage this warp's x sequence into shared (coalesced float4) ----
    {
        const float4* xg = (const float4*)(x + (long long)b * (T_STEPS * NIN));
#pragma unroll
        for (int i = lane; i < (T_STEPS * NIN) / 4; i += 32)
            x4_sh[w][i] = xg[i];
    }

    float c = 0.0f, h = 0.0f;
    h_sh[w][0][lane] = 0.0f;
    __syncwarp();

    const float* xs = (const float*)&x4_sh[w][0];
    int cur = 0;

    for (int t = 0; t < T_STEPS; ++t) {
        // input projection (packed gate pairs)
        const float* xt = xs + t * NIN;
        unsigned long long xif = bias_if, xgo = bias_go;
#pragma unroll
        for (int m = 0; m < NIN; ++m) {
            unsigned long long xm = pack2(xt[m], xt[m]);
            xif = ffma2(wih_if[m], xm, xif);
            xgo = ffma2(wih_go[m], xm, xgo);
        }

        // recurrent GEMV: 64 FFMA2, 4 independent chains
        unsigned long long ai = 0ull, af = 0ull, ag = 0ull, ao = 0ull;
        const unsigned long long* hp =
            (const unsigned long long*)&h_sh[w][cur][0];
#pragma unroll
        for (int k = 0; k < H / 2; ++k) {
            unsigned long long hh = hp[k];
            ai = ffma2(whh_i[k], hh, ai);
            af = ffma2(whh_f[k], hh, af);
            ag = ffma2(whh_g[k], hh, ag);
            ao = ffma2(whh_o[k], hh, ao);
        }

        float aix, aiy, afx, afy, agx, agy, aox, aoy;
        unpack2(ai, aix, aiy);
        unpack2(af, afx, afy);
        unpack2(ag, agx, agy);
        unpack2(ao, aox, aoy);
        float xi, xf, xg2, xo;
        unpack2(xif, xi, xf);
        unpack2(xgo, xg2, xo);

        float gi = sigf(aix + aiy + xi);
        float gf = sigf(afx + afy + xf);
        float gg = tanh_f(agx + agy + xg2);
        float go = sigf(aox + aoy + xo);

        c = gf * c + gi * gg;
        h = go * tanh_f(c);

        h_sh[w][cur ^ 1][lane] = h;
        __syncwarp();
        cur ^= 1;
    }

    // ---- final projection: out[b] = h @ W_fc^T + b_fc ----
    float p0 = h * W_fc[lane];
    float p1 = h * W_fc[H + lane];
#pragma unroll
    for (int off = 16; off; off >>= 1) {
        p0 += __shfl_xor_sync(0xffffffffu, p0, off);
        p1 += __shfl_xor_sync(0xffffffffu, p1, off);
    }
    if (lane == 0) {
        out[2 * b + 0] = p0 + b_fc[0];
        out[2 * b + 1] = p1 + b_fc[1];
    }
}

extern "C" void kernel_launch(void* const* d_in, const int* in_sizes, int n_in,
                              void* d_out, int out_size) {
    const float* x    = (const float*)d_in[0];
    const float* W_ih = (const float*)d_in[1];
    const float* W_hh = (const float*)d_in[2];
    const float* b_ih = (const float*)d_in[3];
    const float* b_hh = (const float*)d_in[4];
    const float* W_fc = (const float*)d_in[5];
    const float* b_fc = (const float*)d_in[6];
    float* out = (float*)d_out;

    int B = in_sizes[0] / (T_STEPS * NIN);
    int blocks = (B + WARPS_PER_BLOCK - 1) / WARPS_PER_BLOCK;
    lstm_kernel<<<blocks, WARPS_PER_BLOCK * 32>>>(x, W_ih, W_hh, b_ih, b_hh,
                                                  W_fc, b_fc, out, B);
}

// round 2
// speedup vs baseline: 1.8403x; 1.8403x over previous
#include <cuda_runtime.h>

#define T_STEPS 200
#define NIN     5
#define H       32
#define WARPS_PER_BLOCK 4
#define BPW     2   // batches per warp (per thread)

// ---- f32x2 packed helpers (sm_103a) ----
__device__ __forceinline__ unsigned long long pack2(float lo, float hi) {
    unsigned long long r;
    asm("mov.b64 %0, {%1, %2};" : "=l"(r) : "f"(lo), "f"(hi));
    return r;
}
__device__ __forceinline__ void unpack2(unsigned long long v, float& lo, float& hi) {
    asm("mov.b64 {%0, %1}, %2;" : "=f"(lo), "=f"(hi) : "l"(v));
}
__device__ __forceinline__ unsigned long long ffma2(unsigned long long a,
                                                    unsigned long long b,
                                                    unsigned long long c) {
    unsigned long long d;
    asm("fma.rn.f32x2 %0, %1, %2, %3;" : "=l"(d) : "l"(a), "l"(b), "l"(c));
    return d;
}

__device__ __forceinline__ float sigf(float x) {
    return __fdividef(1.0f, 1.0f + __expf(-x));
}
__device__ __forceinline__ float tanh_f(float x) {
    return fmaf(2.0f, sigf(2.0f * x), -1.0f);
}

__global__ void __launch_bounds__(WARPS_PER_BLOCK * 32)
lstm_kernel(const float* __restrict__ x,
            const float* __restrict__ W_ih,
            const float* __restrict__ W_hh,
            const float* __restrict__ b_ih,
            const float* __restrict__ b_hh,
            const float* __restrict__ W_fc,
            const float* __restrict__ b_fc,
            float* __restrict__ out,
            int B) {
    // x staging: per warp, BPW batches of 250 float4 each
    __shared__ float4 x4_sh[WARPS_PER_BLOCK][BPW][(T_STEPS * NIN) / 4];
    // h exchange: [warp][double-buffer][batch][H]
    __shared__ __align__(16) float h_sh[WARPS_PER_BLOCK][2][BPW][H];

    const int lane = threadIdx.x & 31;
    const int w    = threadIdx.x >> 5;
    const int b0   = (blockIdx.x * WARPS_PER_BLOCK + w) * BPW;
    if (b0 >= B) return;

    // ---- recurrent weights in registers, packed over K (f32x2) ----
    const int row_i = lane;
    const int row_f = H + lane;
    const int row_g = 2 * H + lane;
    const int row_o = 3 * H + lane;

    unsigned long long whh_i[H / 2], whh_f[H / 2], whh_g[H / 2], whh_o[H / 2];
    {
        const float2* Wi = (const float2*)(W_hh + row_i * H);
        const float2* Wf = (const float2*)(W_hh + row_f * H);
        const float2* Wg = (const float2*)(W_hh + row_g * H);
        const float2* Wo = (const float2*)(W_hh + row_o * H);
#pragma unroll
        for (int k = 0; k < H / 2; ++k) {
            float2 vi = Wi[k], vf = Wf[k], vg = Wg[k], vo = Wo[k];
            whh_i[k] = pack2(vi.x, vi.y);
            whh_f[k] = pack2(vf.x, vf.y);
            whh_g[k] = pack2(vg.x, vg.y);
            whh_o[k] = pack2(vo.x, vo.y);
        }
    }

    unsigned long long wih_if[NIN], wih_go[NIN];
#pragma unroll
    for (int m = 0; m < NIN; ++m) {
        wih_if[m] = pack2(W_ih[row_i * NIN + m], W_ih[row_f * NIN + m]);
        wih_go[m] = pack2(W_ih[row_g * NIN + m], W_ih[row_o * NIN + m]);
    }
    const unsigned long long bias_if =
        pack2(b_ih[row_i] + b_hh[row_i], b_ih[row_f] + b_hh[row_f]);
    const unsigned long long bias_go =
        pack2(b_ih[row_g] + b_hh[row_g], b_ih[row_o] + b_hh[row_o]);

    // ---- stage x for both batches (coalesced float4) ----
#pragma unroll
    for (int bb = 0; bb < BPW; ++bb) {
        const float4* xg =
            (const float4*)(x + (long long)(b0 + bb) * (T_STEPS * NIN));
        for (int i = lane; i < (T_STEPS * NIN) / 4; i += 32)
            x4_sh[w][bb][i] = xg[i];
    }

    float c[BPW], h[BPW];
#pragma unroll
    for (int bb = 0; bb < BPW; ++bb) {
        c[bb] = 0.0f;
        h[bb] = 0.0f;
        h_sh[w][0][bb][lane] = 0.0f;
    }
    __syncwarp();

    int cur = 0;

    for (int t = 0; t < T_STEPS; ++t) {
        // ---- input projections for both batches ----
        unsigned long long xif[BPW], xgo[BPW];
#pragma unroll
        for (int bb = 0; bb < BPW; ++bb) {
            const float* xt = (const float*)&x4_sh[w][bb][0] + t * NIN;
            xif[bb] = bias_if;
            xgo[bb] = bias_go;
#pragma unroll
            for (int m = 0; m < NIN; ++m) {
                unsigned long long xm = pack2(xt[m], xt[m]);
                xif[bb] = ffma2(wih_if[m], xm, xif[bb]);
                xgo[bb] = ffma2(wih_go[m], xm, xgo[bb]);
            }
        }

        // ---- recurrent GEMV: 128 FFMA2, 8 independent chains ----
        unsigned long long ai[BPW], af[BPW], ag[BPW], ao[BPW];
#pragma unroll
        for (int bb = 0; bb < BPW; ++bb)
            ai[bb] = af[bb] = ag[bb] = ao[bb] = 0ull;

        const unsigned long long* hp0 =
            (const unsigned long long*)&h_sh[w][cur][0][0];
        const unsigned long long* hp1 =
            (const unsigned long long*)&h_sh[w][cur][1][0];
#pragma unroll
        for (int k = 0; k < H / 2; ++k) {
            unsigned long long h0 = hp0[k];
            unsigned long long h1 = hp1[k];
            ai[0] = ffma2(whh_i[k], h0, ai[0]);
            ai[1] = ffma2(whh_i[k], h1, ai[1]);
            af[0] = ffma2(whh_f[k], h0, af[0]);
            af[1] = ffma2(whh_f[k], h1, af[1]);
            ag[0] = ffma2(whh_g[k], h0, ag[0]);
            ag[1] = ffma2(whh_g[k], h1, ag[1]);
            ao[0] = ffma2(whh_o[k], h0, ao[0]);
            ao[1] = ffma2(whh_o[k], h1, ao[1]);
        }

        // ---- activations + state update ----
#pragma unroll
        for (int bb = 0; bb < BPW; ++bb) {
            float aix, aiy, afx, afy, agx, agy, aox, aoy;
            unpack2(ai[bb], aix, aiy);
            unpack2(af[bb], afx, afy);
            unpack2(ag[bb], agx, agy);
            unpack2(ao[bb], aox, aoy);
            float xi, xf, xg2, xo;
            unpack2(xif[bb], xi, xf);
            unpack2(xgo[bb], xg2, xo);

            float gi = sigf(aix + aiy + xi);
            float gf = sigf(afx + afy + xf);
            float gg = tanh_f(agx + agy + xg2);
            float go = sigf(aox + aoy + xo);

            c[bb] = gf * c[bb] + gi * gg;
            h[bb] = go * tanh_f(c[bb]);
            h_sh[w][cur ^ 1][bb][lane] = h[bb];
        }
        __syncwarp();
        cur ^= 1;
    }

    // ---- final projection ----
#pragma unroll
    for (int bb = 0; bb < BPW; ++bb) {
        float p0 = h[bb] * W_fc[lane];
        float p1 = h[bb] * W_fc[H + lane];
#pragma unroll
        for (int off = 16; off; off >>= 1) {
            p0 += __shfl_xor_sync(0xffffffffu, p0, off);
            p1 += __shfl_xor_sync(0xffffffffu, p1, off);
        }
        if (lane == 0) {
            out[2 * (b0 + bb) + 0] = p0 + b_fc[0];
            out[2 * (b0 + bb) + 1] = p1 + b_fc[1];
        }
    }
}

extern "C" void kernel_launch(void* const* d_in, const int* in_sizes, int n_in,
                              void* d_out, int out_size) {
    const float* x    = (const float*)d_in[0];
    const float* W_ih = (const float*)d_in[1];
    const float* W_hh = (const float*)d_in[2];
    const float* b_ih = (const float*)d_in[3];
    const float* b_hh = (const float*)d_in[4];
    const float* W_fc = (const float*)d_in[5];
    const float* b_fc = (const float*)d_in[6];
    float* out = (float*)d_out;

    int B = in_sizes[0] / (T_STEPS * NIN);
    int batches_per_block = WARPS_PER_BLOCK * BPW;
    int blocks = (B + batches_per_block - 1) / batches_per_block;
    lstm_kernel<<<blocks, WARPS_PER_BLOCK * 32>>>(x, W_ih, W_hh, b_ih, b_hh,
                                                  W_fc, b_fc, out, B);
}

// round 4
// speedup vs baseline: 2.0060x; 1.0901x over previous
#include <cuda_runtime.h>
#include <cuda_bf16.h>

#define T_STEPS 200
#define NIN     5
#define H       32
#define G4      128          // 4H gates
#define NB      8            // batches per warp (mma n-dim)
#define WARPS   4
#define THREADS (WARPS * 32)

// W pitch: 56 bf16 = 112 B  (28 words -> conflict-free ldmatrix rows)
#define WPITCH  56
#define WBYTES  (G4 * WPITCH * 2)          // 14336 per copy
#define OFF_WLO WBYTES                     // 14336
#define OFF_H   (2 * WBYTES)               // 28672
#define HWARPSZ (2 * 48 * NB * 2)          // hi+lo, 48 k-rows x 8 cols bf16 = 1536
#define HLO     768

struct SmemLayout {
    __nv_bfloat16 Whi[G4][WPITCH];
    __nv_bfloat16 Wlo[G4][WPITCH];
    __nv_bfloat16 Hbuf[WARPS][2][48][NB];  // [warp][hi/lo][k][n]
};

// ---------- PTX helpers ----------
__device__ __forceinline__ unsigned smem_u32(const void* p) {
    unsigned a;
    asm("{ .reg .u64 t; cvta.to.shared.u64 t, %1; cvt.u32.u64 %0, t; }"
        : "=r"(a) : "l"(p));
    return a;
}
__device__ __forceinline__ void ldsm_x4(unsigned& a0, unsigned& a1,
                                        unsigned& a2, unsigned& a3, unsigned addr) {
    asm volatile("ldmatrix.sync.aligned.m8n8.x4.shared.b16 {%0,%1,%2,%3}, [%4];"
                 : "=r"(a0), "=r"(a1), "=r"(a2), "=r"(a3) : "r"(addr));
}
__device__ __forceinline__ void ldsm_x2t(unsigned& b0, unsigned& b1, unsigned addr) {
    asm volatile("ldmatrix.sync.aligned.m8n8.x2.trans.shared.b16 {%0,%1}, [%2];"
                 : "=r"(b0), "=r"(b1) : "r"(addr));
}
#define MMA(Cr, A0, A1, A2, A3, B0, B1)                                        \
    asm volatile("mma.sync.aligned.m16n8k16.row.col.f32.bf16.bf16.f32 "        \
                 "{%0,%1,%2,%3}, {%4,%5,%6,%7}, {%8,%9}, {%0,%1,%2,%3};"       \
                 : "+f"((Cr)[0]), "+f"((Cr)[1]), "+f"((Cr)[2]), "+f"((Cr)[3])  \
                 : "r"(A0), "r"(A1), "r"(A2), "r"(A3), "r"(B0), "r"(B1))

__device__ __forceinline__ void sts32(unsigned addr, unsigned v) {
    asm volatile("st.shared.b32 [%0], %1;" :: "r"(addr), "r"(v) : "memory");
}
__device__ __forceinline__ void sts16(unsigned addr, unsigned short v) {
    asm volatile("st.shared.b16 [%0], %1;" :: "r"(addr), "h"(v) : "memory");
}

// ---------- activation helpers ----------
__device__ __forceinline__ float ex2a(float t) {
    float r; asm("ex2.approx.f32 %0, %1;" : "=f"(r) : "f"(t)); return r;
}
__device__ __forceinline__ float rcpa(float d) {
    float r; asm("rcp.approx.f32 %0, %1;" : "=f"(r) : "f"(d)); return r;
}
__device__ __forceinline__ float rcp_nr(float d) {
    float y = __uint_as_float(0x7EF127EAu - __float_as_uint(d));
    y = y * fmaf(-d, y, 2.0f);
    y = y * fmaf(-d, y, 2.0f);
    return y;
}
__device__ __forceinline__ float sig_m(float x) {     // MUFU-heavy sigmoid
    return rcpa(1.0f + ex2a(-1.442695041f * x));
}
__device__ __forceinline__ float sig_nr(float x) {    // FMA-heavy sigmoid
    return rcp_nr(1.0f + ex2a(-1.442695041f * x));
}
__device__ __forceinline__ float tanh_nr(float x) {
    return fmaf(2.0f, rcp_nr(1.0f + ex2a(-2.885390082f * x)), -1.0f);
}

__global__ void __launch_bounds__(THREADS, 4)
lstm_mma_kernel(const float* __restrict__ x,
                const float* __restrict__ W_ih,
                const float* __restrict__ W_hh,
                const float* __restrict__ b_ih,
                const float* __restrict__ b_hh,
                const float* __restrict__ W_fc,
                const float* __restrict__ b_fc,
                float* __restrict__ out, int B) {
    __shared__ __align__(16) SmemLayout sm;

    const int tid  = threadIdx.x;
    const int wid  = tid >> 5;
    const int lane = tid & 31;

    // ================= init: W hi/lo into smem =================
    {
        const int g = tid;  // 0..127 gate row
        for (int k = 0; k < 48; ++k) {
            float v;
            if (k < H)          v = W_hh[g * H + k];
            else if (k < 37)    v = W_ih[g * NIN + (k - 32)];
            else if (k == 37)   v = b_ih[g] + b_hh[g];
            else                v = 0.0f;
            __nv_bfloat16 hi = __float2bfloat16(v);
            sm.Whi[g][k] = hi;
            sm.Wlo[g][k] = __float2bfloat16(v - __bfloat162float(hi));
        }
    }
    // zero H buffers
    {
        unsigned* hz = (unsigned*)&sm.Hbuf[0][0][0][0];
        for (int i = tid; i < (WARPS * HWARPSZ) / 4; i += THREADS) hz[i] = 0u;
    }
    __syncthreads();
    if (tid < 32)  // row 37 = ones (hi buffer) for every warp's tile
        sm.Hbuf[tid >> 3][0][37][tid & 7] = __float2bfloat16(1.0f);
    __syncthreads();

    const int wb0 = blockIdx.x * (WARPS * NB) + wid * NB;
    if (wb0 >= B) return;   // (only whole warps idle; no CTA syncs below)

    const unsigned sbase = smem_u32(&sm);
    // A-operand (W) ldmatrix lane offset
    const unsigned laneA = (unsigned)(((lane & 7) + ((lane >> 3) & 1) * 8) * (WPITCH * 2)
                                      + (lane >> 4) * 16);
    const unsigned hwarp = sbase + OFF_H + wid * HWARPSZ;
    const unsigned addrB = hwarp + (unsigned)((lane & 15) * 16);
    const int gl = lane >> 2;          // fragment row group 0..7
    const int tl = lane & 3;           // fragment col pair 0..3

    const float* xr = x + (size_t)(wb0 + (lane & 7)) * (T_STEPS * NIN);

    float xv[NIN];
    if (lane < NB) {
#pragma unroll
        for (int d = 0; d < NIN; ++d) xv[d] = xr[d];
    }

    float hreg[8], creg[8];
#pragma unroll
    for (int i = 0; i < 8; ++i) { hreg[i] = 0.0f; creg[i] = 0.0f; }

#pragma unroll 1
    for (int t = 0; t < T_STEPS; ++t) {
        // ---- write h (trunc hi-split + lo) to B-operand smem ----
#pragma unroll
        for (int p = 0; p < 2; ++p)
#pragma unroll
            for (int eh = 0; eh < 2; ++eh) {
                const int idx = p * 4 + eh * 2;
                unsigned h0b = __float_as_uint(hreg[idx]);
                unsigned h1b = __float_as_uint(hreg[idx + 1]);
                unsigned hi32;
                asm("prmt.b32 %0, %1, %2, 0x7632;" : "=r"(hi32) : "r"(h0b), "r"(h1b));
                float lo0 = hreg[idx]     - __uint_as_float(h0b & 0xFFFF0000u);
                float lo1 = hreg[idx + 1] - __uint_as_float(h1b & 0xFFFF0000u);
                unsigned lo32;
                asm("cvt.rn.bf16x2.f32 %0, %1, %2;" : "=r"(lo32) : "f"(lo1), "f"(lo0));
                unsigned ad = hwarp + (unsigned)((16 * p + 8 * eh + gl) * 16 + tl * 4);
                sts32(ad, hi32);
                sts32(ad + HLO, lo32);
            }
        // ---- write x rows (32..36) ----
        if (lane < NB) {
#pragma unroll
            for (int d = 0; d < NIN; ++d) {
                unsigned bits = __float_as_uint(xv[d]);
                unsigned ad = hwarp + (unsigned)((32 + d) * 16 + lane * 2);
                sts16(ad, (unsigned short)(bits >> 16));
                float lo = xv[d] - __uint_as_float(bits & 0xFFFF0000u);
                __nv_bfloat16 lb = __float2bfloat16(lo);
                sts16(ad + HLO, *reinterpret_cast<unsigned short*>(&lb));
            }
        }
        __syncwarp();

        // ---- prefetch next x ----
        if (t + 1 < T_STEPS && lane < NB) {
#pragma unroll
            for (int d = 0; d < NIN; ++d) xv[d] = xr[(t + 1) * NIN + d];
        }

        // ---- 3-pass split MMA:  Whi*Hhi + Wlo*Hhi + Whi*Hlo ----
        float Cacc[8][4];
#pragma unroll
        for (int m = 0; m < 8; ++m)
#pragma unroll
            for (int e = 0; e < 4; ++e) Cacc[m][e] = 0.0f;

#pragma unroll
        for (int kc = 0; kc < 3; ++kc) {
            unsigned bh0, bh1, bl0, bl1;
            ldsm_x2t(bh0, bh1, addrB + kc * 256);
            ldsm_x2t(bl0, bl1, addrB + kc * 256 + HLO);
#pragma unroll
            for (int mt = 0; mt < 8; ++mt) {
                unsigned aw = sbase + laneA + (unsigned)(mt * (16 * WPITCH * 2) + kc * 32);
                unsigned a0, a1, a2, a3, l0, l1, l2, l3;
                ldsm_x4(a0, a1, a2, a3, aw);
                ldsm_x4(l0, l1, l2, l3, aw + OFF_WLO);
                MMA(Cacc[mt], a0, a1, a2, a3, bh0, bh1);
                MMA(Cacc[mt], l0, l1, l2, l3, bh0, bh1);
                MMA(Cacc[mt], a0, a1, a2, a3, bl0, bl1);
            }
        }

        // ---- activations + state update (pipe-balanced) ----
#pragma unroll
        for (int p = 0; p < 2; ++p)
#pragma unroll
            for (int e = 0; e < 4; ++e) {
                const int idx = p * 4 + e;
                float gi = sig_m(Cacc[p][e]);
                float gf = sig_m(Cacc[p + 2][e]);
                float gg = tanh_nr(Cacc[p + 4][e]);
                float go = sig_nr(Cacc[p + 6][e]);
                float cn = fmaf(gf, creg[idx], gi * gg);
                creg[idx] = cn;
                hreg[idx] = go * tanh_nr(cn);
            }
    }

    // ================= final projection =================
    float pA0 = 0.0f, pA1 = 0.0f, pB0 = 0.0f, pB1 = 0.0f;
#pragma unroll
    for (int p = 0; p < 2; ++p)
#pragma unroll
        for (int eh = 0; eh < 2; ++eh) {
            const int u = 16 * p + 8 * eh + gl;
            const float w0 = W_fc[u], w1 = W_fc[H + u];
            const int idx = p * 4 + eh * 2;
            pA0 = fmaf(hreg[idx], w0, pA0);
            pA1 = fmaf(hreg[idx], w1, pA1);
            pB0 = fmaf(hreg[idx + 1], w0, pB0);
            pB1 = fmaf(hreg[idx + 1], w1, pB1);
        }
#pragma unroll
    for (int off = 4; off <= 16; off <<= 1) {
        pA0 += __shfl_xor_sync(0xffffffffu, pA0, off);
        pA1 += __shfl_xor_sync(0xffffffffu, pA1, off);
        pB0 += __shfl_xor_sync(0xffffffffu, pB0, off);
        pB1 += __shfl_xor_sync(0xffffffffu, pB1, off);
    }
    if (lane < 4) {
        const int bA = wb0 + 2 * lane, bB = bA + 1;
        const float f0 = b_fc[0], f1 = b_fc[1];
        out[bA * 2 + 0] = pA0 + f0;
        out[bA * 2 + 1] = pA1 + f1;
        out[bB * 2 + 0] = pB0 + f0;
        out[bB * 2 + 1] = pB1 + f1;
    }
}

extern "C" void kernel_launch(void* const* d_in, const int* in_sizes, int n_in,
                              void* d_out, int out_size) {
    const float* x    = (const float*)d_in[0];
    const float* W_ih = (const float*)d_in[1];
    const float* W_hh = (const float*)d_in[2];
    const float* b_ih = (const float*)d_in[3];
    const float* b_hh = (const float*)d_in[4];
    const float* W_fc = (const float*)d_in[5];
    const float* b_fc = (const float*)d_in[6];
    float* out = (float*)d_out;

    int B = in_sizes[0] / (T_STEPS * NIN);
    int bpc = WARPS * NB;                      // 32 batches per CTA
    int blocks = (B + bpc - 1) / bpc;
    lstm_mma_kernel<<<blocks, THREADS>>>(x, W_ih, W_hh, b_ih, b_hh,
                                         W_fc, b_fc, out, B);
}

// round 5
// speedup vs baseline: 3.7837x; 1.8862x over previous
#include <cuda_runtime.h>
#include <cuda_fp16.h>

#define T_STEPS 200
#define NIN     5
#define H       32
#define G4      128          // 4H gate rows
#define NB      16           // batches per warp (2 n-tiles)
#define WARPS   4
#define THREADS (WARPS * 32)

#define WPITCH  56                        // halfs per W row (112 B, LDSM conflict-free)
#define WBYTES  (G4 * WPITCH * 2)         // 14336 per copy
#define OFF_WLO WBYTES
#define OFF_H   (2 * WBYTES)              // 28672
#define HPITCH  48                        // bytes per Hbuf row (24 halfs; conflict-free)
#define HWARPSZ (48 * HPITCH)             // 2304 per warp

struct SmemLayout {
    __half Whi[G4][WPITCH];
    __half Wlo[G4][WPITCH];
    __half Hbuf[WARPS][48][HPITCH / 2];   // [k-row][n-col(+pad)]
};

// ---------- PTX helpers ----------
__device__ __forceinline__ unsigned smem_u32(const void* p) {
    unsigned a;
    asm("{ .reg .u64 t; cvta.to.shared.u64 t, %1; cvt.u32.u64 %0, t; }"
        : "=r"(a) : "l"(p));
    return a;
}
__device__ __forceinline__ void ldsm_x4(unsigned& a0, unsigned& a1,
                                        unsigned& a2, unsigned& a3, unsigned addr) {
    asm volatile("ldmatrix.sync.aligned.m8n8.x4.shared.b16 {%0,%1,%2,%3}, [%4];"
                 : "=r"(a0), "=r"(a1), "=r"(a2), "=r"(a3) : "r"(addr));
}
__device__ __forceinline__ void ldsm_x4t(unsigned& b0, unsigned& b1,
                                         unsigned& b2, unsigned& b3, unsigned addr) {
    asm volatile("ldmatrix.sync.aligned.m8n8.x4.trans.shared.b16 {%0,%1,%2,%3}, [%4];"
                 : "=r"(b0), "=r"(b1), "=r"(b2), "=r"(b3) : "r"(addr));
}
#define MMA(Cr, A0, A1, A2, A3, B0, B1)                                        \
    asm volatile("mma.sync.aligned.m16n8k16.row.col.f32.f16.f16.f32 "          \
                 "{%0,%1,%2,%3}, {%4,%5,%6,%7}, {%8,%9}, {%0,%1,%2,%3};"       \
                 : "+f"((Cr)[0]), "+f"((Cr)[1]), "+f"((Cr)[2]), "+f"((Cr)[3])  \
                 : "r"(A0), "r"(A1), "r"(A2), "r"(A3), "r"(B0), "r"(B1))

__device__ __forceinline__ void sts32(unsigned addr, unsigned v) {
    asm volatile("st.shared.b32 [%0], %1;" :: "r"(addr), "r"(v) : "memory");
}
__device__ __forceinline__ void sts16(unsigned addr, unsigned short v) {
    asm volatile("st.shared.b16 [%0], %1;" :: "r"(addr), "h"(v) : "memory");
}
// pack (even->low, odd->high)
__device__ __forceinline__ unsigned pack_f16x2(float odd, float even) {
    unsigned r;
    asm("cvt.rn.f16x2.f32 %0, %1, %2;" : "=r"(r) : "f"(odd), "f"(even));
    return r;
}

// ---------- activation helpers (same as R4: measured rel_err 2.4e-5) ----------
__device__ __forceinline__ float ex2a(float t) {
    float r; asm("ex2.approx.f32 %0, %1;" : "=f"(r) : "f"(t)); return r;
}
__device__ __forceinline__ float rcpa(float d) {
    float r; asm("rcp.approx.f32 %0, %1;" : "=f"(r) : "f"(d)); return r;
}
__device__ __forceinline__ float rcp_nr(float d) {
    float y = __uint_as_float(0x7EF127EAu - __float_as_uint(d));
    y = y * fmaf(-d, y, 2.0f);
    y = y * fmaf(-d, y, 2.0f);
    return y;
}
__device__ __forceinline__ float sig_m(float x) {     // MUFU-heavy
    return rcpa(1.0f + ex2a(-1.442695041f * x));
}
__device__ __forceinline__ float sig_nr(float x) {    // FMA-heavy
    return rcp_nr(1.0f + ex2a(-1.442695041f * x));
}
__device__ __forceinline__ float tanh_nr(float x) {
    return fmaf(2.0f, rcp_nr(1.0f + ex2a(-2.885390082f * x)), -1.0f);
}

__global__ void __launch_bounds__(THREADS, 2)
lstm_mma16_kernel(const float* __restrict__ x,
                  const float* __restrict__ W_ih,
                  const float* __restrict__ W_hh,
                  const float* __restrict__ b_ih,
                  const float* __restrict__ b_hh,
                  const float* __restrict__ W_fc,
                  const float* __restrict__ b_fc,
                  float* __restrict__ out, int B) {
    __shared__ __align__(16) SmemLayout sm;

    const int tid  = threadIdx.x;
    const int wid  = tid >> 5;
    const int lane = tid & 31;

    // ============ init: W hi/lo (fp16 split) ============
    {
        const int g = tid;  // 0..127
        for (int k = 0; k < WPITCH; ++k) {
            float v;
            if (k < H)            v = W_hh[g * H + k];
            else if (k < 37)      v = W_ih[g * NIN + (k - 32)];
            else if (k == 37)     v = b_ih[g] + b_hh[g];
            else if (k >= 38 && k < 43) v = W_ih[g * NIN + (k - 38)]; // x_lo columns
            else                  v = 0.0f;
            __half hi = __float2half(v);
            sm.Whi[g][k] = hi;
            sm.Wlo[g][k] = __float2half(v - __half2float(hi));
        }
    }
    {   // zero H buffers
        unsigned* hz = (unsigned*)&sm.Hbuf[0][0][0];
        for (int i = tid; i < (WARPS * HWARPSZ) / 4; i += THREADS) hz[i] = 0u;
    }
    __syncthreads();
    if (tid < WARPS * NB)   // ones row (k=37) per warp tile
        sm.Hbuf[tid / NB][37][tid % NB] = __float2half(1.0f);
    __syncthreads();

    const int wb0 = blockIdx.x * (WARPS * NB) + wid * NB;
    if (wb0 >= B) return;   // no CTA syncs below

    const unsigned sbase = smem_u32(&sm);
    const unsigned laneA = (unsigned)((lane & 15) * (WPITCH * 2) + (lane >> 4) * 16);
    const unsigned hwarp = sbase + OFF_H + wid * HWARPSZ;
    const unsigned addrB = hwarp + (unsigned)((lane & 15) * HPITCH + (lane >> 4) * 16);
    const int gl = lane >> 2;          // fragment row 0..7
    const int tl = lane & 3;           // fragment col pair 0..3

    const float* xr = x + (size_t)(wb0 + lane) * (T_STEPS * NIN);  // valid for lane<16

    float xv[NIN];
    if (lane < NB) {
#pragma unroll
        for (int d = 0; d < NIN; ++d) xv[d] = xr[d];
    }

    // state: idx = 8p + 4rr + 2nt + e  (unit u = p*16+rr*8+gl, col n = nt*8+2tl+e)
    float hreg[16], creg[16];
#pragma unroll
    for (int i = 0; i < 16; ++i) { hreg[i] = 0.0f; creg[i] = 0.0f; }

#pragma unroll 1
    for (int t = 0; t < T_STEPS; ++t) {
        // ---- write h (single fp16) to B-operand smem ----
#pragma unroll
        for (int p = 0; p < 2; ++p)
#pragma unroll
            for (int rr = 0; rr < 2; ++rr) {
                const int u = p * 16 + rr * 8 + gl;
                const int base = 8 * p + 4 * rr;
#pragma unroll
                for (int nt = 0; nt < 2; ++nt) {
                    unsigned v = pack_f16x2(hreg[base + 2 * nt + 1],
                                            hreg[base + 2 * nt]);
                    sts32(hwarp + (unsigned)(u * HPITCH + (nt * 8 + 2 * tl) * 2), v);
                }
            }
        // ---- write x rows: hi at k=32..36, lo at k=38..42 ----
        if (lane < NB) {
#pragma unroll
            for (int d = 0; d < NIN; ++d) {
                __half xh = __float2half(xv[d]);
                __half xl = __float2half(xv[d] - __half2float(xh));
                sts16(hwarp + (unsigned)((32 + d) * HPITCH + lane * 2),
                      *reinterpret_cast<unsigned short*>(&xh));
                sts16(hwarp + (unsigned)((38 + d) * HPITCH + lane * 2),
                      *reinterpret_cast<unsigned short*>(&xl));
            }
        }
        __syncwarp();

        // ---- prefetch next x ----
        if (t + 1 < T_STEPS && lane < NB) {
#pragma unroll
            for (int d = 0; d < NIN; ++d) xv[d] = xr[(t + 1) * NIN + d];
        }

        // ---- 2-pass split MMA: (Whi + Wlo) x H ----
        float Cacc[8][2][4];
#pragma unroll
        for (int m = 0; m < 8; ++m)
#pragma unroll
            for (int n = 0; n < 2; ++n)
#pragma unroll
                for (int e = 0; e < 4; ++e) Cacc[m][n][e] = 0.0f;

#pragma unroll
        for (int kc = 0; kc < 3; ++kc) {
            unsigned rb0, rb1, rb2, rb3;
            ldsm_x4t(rb0, rb1, rb2, rb3, addrB + (unsigned)(kc * 16 * HPITCH));
#pragma unroll
            for (int mt = 0; mt < 8; ++mt) {
                unsigned aw = sbase + laneA +
                              (unsigned)(mt * (16 * WPITCH * 2) + kc * 32);
                unsigned a0, a1, a2, a3, l0, l1, l2, l3;
                ldsm_x4(a0, a1, a2, a3, aw);
                ldsm_x4(l0, l1, l2, l3, aw + OFF_WLO);
                MMA(Cacc[mt][0], a0, a1, a2, a3, rb0, rb1);
                MMA(Cacc[mt][0], l0, l1, l2, l3, rb0, rb1);
                MMA(Cacc[mt][1], a0, a1, a2, a3, rb2, rb3);
                MMA(Cacc[mt][1], l0, l1, l2, l3, rb2, rb3);
            }
        }

        // ---- activations + state update ----
#pragma unroll
        for (int p = 0; p < 2; ++p)
#pragma unroll
            for (int nt = 0; nt < 2; ++nt)
#pragma unroll
                for (int rr = 0; rr < 2; ++rr)
#pragma unroll
                    for (int e = 0; e < 2; ++e) {
                        const int j = rr * 2 + e;
                        const int idx = 8 * p + 4 * rr + 2 * nt + e;
                        float gi = sig_m(Cacc[p][nt][j]);
                        float gf = sig_m(Cacc[2 + p][nt][j]);
                        float gg = tanh_nr(Cacc[4 + p][nt][j]);
                        float go = sig_nr(Cacc[6 + p][nt][j]);
                        float cn = fmaf(gf, creg[idx], gi * gg);
                        creg[idx] = cn;
                        hreg[idx] = go * tanh_nr(cn);
                    }
    }

    // ============ final projection ============
    float acc[4][2];
#pragma unroll
    for (int q = 0; q < 4; ++q) { acc[q][0] = 0.0f; acc[q][1] = 0.0f; }
#pragma unroll
    for (int p = 0; p < 2; ++p)
#pragma unroll
        for (int rr = 0; rr < 2; ++rr) {
            const int u = p * 16 + rr * 8 + gl;
            const float w0 = W_fc[u], w1 = W_fc[H + u];
#pragma unroll
            for (int nt = 0; nt < 2; ++nt)
#pragma unroll
                for (int e = 0; e < 2; ++e) {
                    const int idx = 8 * p + 4 * rr + 2 * nt + e;
                    acc[nt * 2 + e][0] = fmaf(hreg[idx], w0, acc[nt * 2 + e][0]);
                    acc[nt * 2 + e][1] = fmaf(hreg[idx], w1, acc[nt * 2 + e][1]);
                }
        }
#pragma unroll
    for (int off = 4; off <= 16; off <<= 1)
#pragma unroll
        for (int q = 0; q < 4; ++q) {
            acc[q][0] += __shfl_xor_sync(0xffffffffu, acc[q][0], off);
            acc[q][1] += __shfl_xor_sync(0xffffffffu, acc[q][1], off);
        }
    if (lane < 4) {   // lane == tl, gl == 0
        const float f0 = b_fc[0], f1 = b_fc[1];
#pragma unroll
        for (int nt = 0; nt < 2; ++nt)
#pragma unroll
            for (int e = 0; e < 2; ++e) {
                const int col = nt * 8 + 2 * lane + e;
                out[(wb0 + col) * 2 + 0] = acc[nt * 2 + e][0] + f0;
                out[(wb0 + col) * 2 + 1] = acc[nt * 2 + e][1] + f1;
            }
    }
}

extern "C" void kernel_launch(void* const* d_in, const int* in_sizes, int n_in,
                              void* d_out, int out_size) {
    const float* x    = (const float*)d_in[0];
    const float* W_ih = (const float*)d_in[1];
    const float* W_hh = (const float*)d_in[2];
    const float* b_ih = (const float*)d_in[3];
    const float* b_hh = (const float*)d_in[4];
    const float* W_fc = (const float*)d_in[5];
    const float* b_fc = (const float*)d_in[6];
    float* out = (float*)d_out;

    int B = in_sizes[0] / (T_STEPS * NIN);
    int bpc = WARPS * NB;                      // 64 batches per CTA
    int blocks = (B + bpc - 1) / bpc;
    lstm_mma16_kernel<<<blocks, THREADS>>>(x, W_ih, W_hh, b_ih, b_hh,
                                           W_fc, b_fc, out, B);
}

// round 6
// speedup vs baseline: 3.8210x; 1.0099x over previous
#include <cuda_runtime.h>
#include <cuda_fp16.h>

#define T_STEPS 200
#define NIN     5
#define H       32
#define G4      128          // 4H gate rows
#define NB      16           // batches per warp (2 n-tiles)
#define WARPS   4
#define THREADS (WARPS * 32)

#define WPITCH  56                        // halfs per W row (112 B, LDSM conflict-free)
#define WBYTES  (G4 * WPITCH * 2)         // 14336 per copy
#define OFF_WLO WBYTES
#define OFF_H   (2 * WBYTES)              // 28672
#define HPITCH  48                        // bytes per Hbuf row
#define HWARPSZ (48 * HPITCH)             // 2304 per warp

struct SmemLayout {
    __half Whi[G4][WPITCH];
    __half Wlo[G4][WPITCH];
    __half Hbuf[WARPS][48][HPITCH / 2];
};

// ---------- PTX helpers ----------
__device__ __forceinline__ unsigned smem_u32(const void* p) {
    unsigned a;
    asm("{ .reg .u64 t; cvta.to.shared.u64 t, %1; cvt.u32.u64 %0, t; }"
        : "=r"(a) : "l"(p));
    return a;
}
__device__ __forceinline__ void ldsm_x4(unsigned& a0, unsigned& a1,
                                        unsigned& a2, unsigned& a3, unsigned addr) {
    asm volatile("ldmatrix.sync.aligned.m8n8.x4.shared.b16 {%0,%1,%2,%3}, [%4];"
                 : "=r"(a0), "=r"(a1), "=r"(a2), "=r"(a3) : "r"(addr));
}
__device__ __forceinline__ void ldsm_x4t(unsigned& b0, unsigned& b1,
                                         unsigned& b2, unsigned& b3, unsigned addr) {
    asm volatile("ldmatrix.sync.aligned.m8n8.x4.trans.shared.b16 {%0,%1,%2,%3}, [%4];"
                 : "=r"(b0), "=r"(b1), "=r"(b2), "=r"(b3) : "r"(addr));
}
#define MMA(Cr, A0, A1, A2, A3, B0, B1)                                        \
    asm volatile("mma.sync.aligned.m16n8k16.row.col.f32.f16.f16.f32 "          \
                 "{%0,%1,%2,%3}, {%4,%5,%6,%7}, {%8,%9}, {%0,%1,%2,%3};"       \
                 : "+f"((Cr)[0]), "+f"((Cr)[1]), "+f"((Cr)[2]), "+f"((Cr)[3])  \
                 : "r"(A0), "r"(A1), "r"(A2), "r"(A3), "r"(B0), "r"(B1))

__device__ __forceinline__ void sts32(unsigned addr, unsigned v) {
    asm volatile("st.shared.b32 [%0], %1;" :: "r"(addr), "r"(v) : "memory");
}
__device__ __forceinline__ void sts16(unsigned addr, unsigned short v) {
    asm volatile("st.shared.b16 [%0], %1;" :: "r"(addr), "h"(v) : "memory");
}
__device__ __forceinline__ unsigned pack_f16x2(float odd, float even) {
    unsigned r;
    asm("cvt.rn.f16x2.f32 %0, %1, %2;" : "=r"(r) : "f"(odd), "f"(even));
    return r;
}

// ---------- activation helpers (proven: rel_err 2.7e-5) ----------
__device__ __forceinline__ float ex2a(float t) {
    float r; asm("ex2.approx.f32 %0, %1;" : "=f"(r) : "f"(t)); return r;
}
__device__ __forceinline__ float rcpa(float d) {
    float r; asm("rcp.approx.f32 %0, %1;" : "=f"(r) : "f"(d)); return r;
}
__device__ __forceinline__ float rcp_nr(float d) {
    float y = __uint_as_float(0x7EF127EAu - __float_as_uint(d));
    y = y * fmaf(-d, y, 2.0f);
    y = y * fmaf(-d, y, 2.0f);
    return y;
}
__device__ __forceinline__ float sig_m(float x) {     // MUFU-heavy
    return rcpa(1.0f + ex2a(-1.442695041f * x));
}
__device__ __forceinline__ float sig_nr(float x) {    // FMA-heavy
    return rcp_nr(1.0f + ex2a(-1.442695041f * x));
}
__device__ __forceinline__ float tanh_nr(float x) {
    return fmaf(2.0f, rcp_nr(1.0f + ex2a(-2.885390082f * x)), -1.0f);
}

__global__ void __launch_bounds__(THREADS, 2)
lstm_mma16r_kernel(const float* __restrict__ x,
                   const float* __restrict__ W_ih,
                   const float* __restrict__ W_hh,
                   const float* __restrict__ b_ih,
                   const float* __restrict__ b_hh,
                   const float* __restrict__ W_fc,
                   const float* __restrict__ b_fc,
                   float* __restrict__ out, int B) {
    __shared__ __align__(16) SmemLayout sm;

    const int tid  = threadIdx.x;
    const int wid  = tid >> 5;
    const int lane = tid & 31;

    // ============ init: W hi/lo (fp16 split) ============
    {
        const int g = tid;  // 0..127
        for (int k = 0; k < WPITCH; ++k) {
            float v;
            if (k < H)            v = W_hh[g * H + k];
            else if (k < 37)      v = W_ih[g * NIN + (k - 32)];
            else if (k == 37)     v = b_ih[g] + b_hh[g];
            else if (k >= 38 && k < 43) v = W_ih[g * NIN + (k - 38)]; // x_lo cols
            else                  v = 0.0f;
            __half hi = __float2half(v);
            sm.Whi[g][k] = hi;
            sm.Wlo[g][k] = __float2half(v - __half2float(hi));
        }
    }
    {   // zero H buffers
        unsigned* hz = (unsigned*)&sm.Hbuf[0][0][0];
        for (int i = tid; i < (WARPS * HWARPSZ) / 4; i += THREADS) hz[i] = 0u;
    }
    __syncthreads();
    if (tid < WARPS * NB)
        sm.Hbuf[tid / NB][37][tid % NB] = __float2half(1.0f);
    __syncthreads();

    const int wb0 = blockIdx.x * (WARPS * NB) + wid * NB;
    if (wb0 >= B) return;

    const unsigned sbase = smem_u32(&sm);
    const unsigned laneA = (unsigned)((lane & 15) * (WPITCH * 2) + (lane >> 4) * 16);
    const unsigned hwarp = sbase + OFF_H + wid * HWARPSZ;
    const unsigned addrB = hwarp + (unsigned)((lane & 15) * HPITCH + (lane >> 4) * 16);
    const int gl = lane >> 2;
    const int tl = lane & 3;

    // ---- pin Whi fragments in registers (step-invariant) ----
    unsigned wa[8][3][4];
#pragma unroll
    for (int mt = 0; mt < 8; ++mt)
#pragma unroll
        for (int kc = 0; kc < 3; ++kc)
            ldsm_x4(wa[mt][kc][0], wa[mt][kc][1], wa[mt][kc][2], wa[mt][kc][3],
                    sbase + laneA + (unsigned)(mt * (16 * WPITCH * 2) + kc * 32));

    const float* xr = x + (size_t)(wb0 + lane) * (T_STEPS * NIN);  // lane<16 valid

    float xv[NIN];
    if (lane < NB) {
#pragma unroll
        for (int d = 0; d < NIN; ++d) xv[d] = xr[d];
    }

    float hreg[16], creg[16];
#pragma unroll
    for (int i = 0; i < 16; ++i) { hreg[i] = 0.0f; creg[i] = 0.0f; }

#pragma unroll 1
    for (int t = 0; t < T_STEPS; ++t) {
        // ---- write h (fp16) ----
#pragma unroll
        for (int p = 0; p < 2; ++p)
#pragma unroll
            for (int rr = 0; rr < 2; ++rr) {
                const int u = p * 16 + rr * 8 + gl;
                const int base = 8 * p + 4 * rr;
#pragma unroll
                for (int nt = 0; nt < 2; ++nt) {
                    unsigned v = pack_f16x2(hreg[base + 2 * nt + 1],
                                            hreg[base + 2 * nt]);
                    sts32(hwarp + (unsigned)(u * HPITCH + (nt * 8 + 2 * tl) * 2), v);
                }
            }
        // ---- write x rows: hi at 32..36, lo at 38..42 ----
        if (lane < NB) {
#pragma unroll
            for (int d = 0; d < NIN; ++d) {
                __half xh = __float2half(xv[d]);
                __half xl = __float2half(xv[d] - __half2float(xh));
                sts16(hwarp + (unsigned)((32 + d) * HPITCH + lane * 2),
                      *reinterpret_cast<unsigned short*>(&xh));
                sts16(hwarp + (unsigned)((38 + d) * HPITCH + lane * 2),
                      *reinterpret_cast<unsigned short*>(&xl));
            }
        }
        __syncwarp();

        // ---- prefetch next x ----
        if (t + 1 < T_STEPS && lane < NB) {
#pragma unroll
            for (int d = 0; d < NIN; ++d) xv[d] = xr[(t + 1) * NIN + d];
        }

        // ---- 2-pass split MMA: hi pass from registers, lo pass from smem ----
        float Cacc[8][2][4];
#pragma unroll
        for (int m = 0; m < 8; ++m)
#pragma unroll
            for (int n = 0; n < 2; ++n)
#pragma unroll
                for (int e = 0; e < 4; ++e) Cacc[m][n][e] = 0.0f;

#pragma unroll
        for (int kc = 0; kc < 3; ++kc) {
            unsigned rb0, rb1, rb2, rb3;
            ldsm_x4t(rb0, rb1, rb2, rb3, addrB + (unsigned)(kc * 16 * HPITCH));
            // hi pass: no LDSM dependency
#pragma unroll
            for (int mt = 0; mt < 8; ++mt) {
                MMA(Cacc[mt][0], wa[mt][kc][0], wa[mt][kc][1],
                    wa[mt][kc][2], wa[mt][kc][3], rb0, rb1);
                MMA(Cacc[mt][1], wa[mt][kc][0], wa[mt][kc][1],
                    wa[mt][kc][2], wa[mt][kc][3], rb2, rb3);
            }
            // lo pass: streamed from smem
#pragma unroll
            for (int mt = 0; mt < 8; ++mt) {
                unsigned l0, l1, l2, l3;
                ldsm_x4(l0, l1, l2, l3,
                        sbase + OFF_WLO + laneA +
                        (unsigned)(mt * (16 * WPITCH * 2) + kc * 32));
                MMA(Cacc[mt][0], l0, l1, l2, l3, rb0, rb1);
                MMA(Cacc[mt][1], l0, l1, l2, l3, rb2, rb3);
            }
        }

        // ---- activations + state update ----
#pragma unroll
        for (int p = 0; p < 2; ++p)
#pragma unroll
            for (int nt = 0; nt < 2; ++nt)
#pragma unroll
                for (int rr = 0; rr < 2; ++rr)
#pragma unroll
                    for (int e = 0; e < 2; ++e) {
                        const int j = rr * 2 + e;
                        const int idx = 8 * p + 4 * rr + 2 * nt + e;
                        float gi = sig_m(Cacc[p][nt][j]);
                        float gf = sig_m(Cacc[2 + p][nt][j]);
                        float gg = tanh_nr(Cacc[4 + p][nt][j]);
                        float go = sig_nr(Cacc[6 + p][nt][j]);
                        float cn = fmaf(gf, creg[idx], gi * gg);
                        creg[idx] = cn;
                        hreg[idx] = go * tanh_nr(cn);
                    }
    }

    // ============ final projection ============
    float acc[4][2];
#pragma unroll
    for (int q = 0; q < 4; ++q) { acc[q][0] = 0.0f; acc[q][1] = 0.0f; }
#pragma unroll
    for (int p = 0; p < 2; ++p)
#pragma unroll
        for (int rr = 0; rr < 2; ++rr) {
            const int u = p * 16 + rr * 8 + gl;
            const float w0 = W_fc[u], w1 = W_fc[H + u];
#pragma unroll
            for (int nt = 0; nt < 2; ++nt)
#pragma unroll
                for (int e = 0; e < 2; ++e) {
                    const int idx = 8 * p + 4 * rr + 2 * nt + e;
                    acc[nt * 2 + e][0] = fmaf(hreg[idx], w0, acc[nt * 2 + e][0]);
                    acc[nt * 2 + e][1] = fmaf(hreg[idx], w1, acc[nt * 2 + e][1]);
                }
        }
#pragma unroll
    for (int off = 4; off <= 16; off <<= 1)
#pragma unroll
        for (int q = 0; q < 4; ++q) {
            acc[q][0] += __shfl_xor_sync(0xffffffffu, acc[q][0], off);
            acc[q][1] += __shfl_xor_sync(0xffffffffu, acc[q][1], off);
        }
    if (lane < 4) {
        const float f0 = b_fc[0], f1 = b_fc[1];
#pragma unroll
        for (int nt = 0; nt < 2; ++nt)
#pragma unroll
            for (int e = 0; e < 2; ++e) {
                const int col = nt * 8 + 2 * lane + e;
                out[(wb0 + col) * 2 + 0] = acc[nt * 2 + e][0] + f0;
                out[(wb0 + col) * 2 + 1] = acc[nt * 2 + e][1] + f1;
            }
    }
}

extern "C" void kernel_launch(void* const* d_in, const int* in_sizes, int n_in,
                              void* d_out, int out_size) {
    const float* x    = (const float*)d_in[0];
    const float* W_ih = (const float*)d_in[1];
    const float* W_hh = (const float*)d_in[2];
    const float* b_ih = (const float*)d_in[3];
    const float* b_hh = (const float*)d_in[4];
    const float* W_fc = (const float*)d_in[5];
    const float* b_fc = (const float*)d_in[6];
    float* out = (float*)d_out;

    int B = in_sizes[0] / (T_STEPS * NIN);
    int bpc = WARPS * NB;                      // 64 batches per CTA
    int blocks = (B + bpc - 1) / bpc;
    lstm_mma16r_kernel<<<blocks, THREADS>>>(x, W_ih, W_hh, b_ih, b_hh,
                                            W_fc, b_fc, out, B);
}

// round 7
// speedup vs baseline: 7.3539x; 1.9246x over previous
#include <cuda_runtime.h>
#include <cuda_fp16.h>

#define T_STEPS 200
#define NIN     5
#define H       32
#define G4      128          // 4H gate rows
#define NB      16           // batches per warp (2 n-tiles)
#define WARPS   4
#define THREADS (WARPS * 32)

#define WPITCH  56                        // halfs per W row (112 B, LDSM conflict-free)
#define WBYTES  (G4 * WPITCH * 2)         // 14336
#define OFF_H   WBYTES
#define HPITCH  48                        // bytes per Hbuf row
#define HWARPSZ (48 * HPITCH)             // 2304 per warp

struct SmemLayout {
    __half Whi[G4][WPITCH];
    __half Hbuf[WARPS][48][HPITCH / 2];
};

// ---------- PTX helpers ----------
__device__ __forceinline__ unsigned smem_u32(const void* p) {
    unsigned a;
    asm("{ .reg .u64 t; cvta.to.shared.u64 t, %1; cvt.u32.u64 %0, t; }"
        : "=r"(a) : "l"(p));
    return a;
}
__device__ __forceinline__ void ldsm_x4(unsigned& a0, unsigned& a1,
                                        unsigned& a2, unsigned& a3, unsigned addr) {
    asm volatile("ldmatrix.sync.aligned.m8n8.x4.shared.b16 {%0,%1,%2,%3}, [%4];"
                 : "=r"(a0), "=r"(a1), "=r"(a2), "=r"(a3) : "r"(addr));
}
__device__ __forceinline__ void ldsm_x4t(unsigned& b0, unsigned& b1,
                                         unsigned& b2, unsigned& b3, unsigned addr) {
    asm volatile("ldmatrix.sync.aligned.m8n8.x4.trans.shared.b16 {%0,%1,%2,%3}, [%4];"
                 : "=r"(b0), "=r"(b1), "=r"(b2), "=r"(b3) : "r"(addr));
}
#define MMA(Cr, A0, A1, A2, A3, B0, B1)                                        \
    asm volatile("mma.sync.aligned.m16n8k16.row.col.f32.f16.f16.f32 "          \
                 "{%0,%1,%2,%3}, {%4,%5,%6,%7}, {%8,%9}, {%0,%1,%2,%3};"       \
                 : "+f"((Cr)[0]), "+f"((Cr)[1]), "+f"((Cr)[2]), "+f"((Cr)[3])  \
                 : "r"(A0), "r"(A1), "r"(A2), "r"(A3), "r"(B0), "r"(B1))

__device__ __forceinline__ void sts32(unsigned addr, unsigned v) {
    asm volatile("st.shared.b32 [%0], %1;" :: "r"(addr), "r"(v) : "memory");
}
__device__ __forceinline__ void sts16(unsigned addr, unsigned short v) {
    asm volatile("st.shared.b16 [%0], %1;" :: "r"(addr), "h"(v) : "memory");
}
__device__ __forceinline__ unsigned pack_f16x2(float odd, float even) {
    unsigned r;
    asm("cvt.rn.f16x2.f32 %0, %1, %2;" : "=r"(r) : "f"(odd), "f"(even));
    return r;
}

// ---------- activations: MUFU.TANH everywhere ----------
__device__ __forceinline__ float tanha(float x) {
    float r; asm("tanh.approx.f32 %0, %1;" : "=f"(r) : "f"(x)); return r;
}
__device__ __forceinline__ float sig_t(float x) {
    return fmaf(0.5f, tanha(0.5f * x), 0.5f);
}

__global__ void __launch_bounds__(THREADS, 2)
lstm_mma1p_kernel(const float* __restrict__ x,
                  const float* __restrict__ W_ih,
                  const float* __restrict__ W_hh,
                  const float* __restrict__ b_ih,
                  const float* __restrict__ b_hh,
                  const float* __restrict__ W_fc,
                  const float* __restrict__ b_fc,
                  float* __restrict__ out, int B) {
    __shared__ __align__(16) SmemLayout sm;

    const int tid  = threadIdx.x;
    const int wid  = tid >> 5;
    const int lane = tid & 31;

    // ============ init: W (fp16, x_lo duplicated cols for x precision) ============
    {
        const int g = tid;  // 0..127
        for (int k = 0; k < WPITCH; ++k) {
            float v;
            if (k < H)            v = W_hh[g * H + k];
            else if (k < 37)      v = W_ih[g * NIN + (k - 32)];
            else if (k == 37)     v = b_ih[g] + b_hh[g];
            else if (k >= 38 && k < 43) v = W_ih[g * NIN + (k - 38)]; // x_lo cols
            else                  v = 0.0f;
            sm.Whi[g][k] = __float2half(v);
        }
    }
    {   // zero H buffers
        unsigned* hz = (unsigned*)&sm.Hbuf[0][0][0];
        for (int i = tid; i < (WARPS * HWARPSZ) / 4; i += THREADS) hz[i] = 0u;
    }
    __syncthreads();
    if (tid < WARPS * NB)
        sm.Hbuf[tid / NB][37][tid % NB] = __float2half(1.0f);
    __syncthreads();

    const int wb0 = blockIdx.x * (WARPS * NB) + wid * NB;
    if (wb0 >= B) return;

    const unsigned sbase = smem_u32(&sm);
    const unsigned laneA = (unsigned)((lane & 15) * (WPITCH * 2) + (lane >> 4) * 16);
    const unsigned hwarp = sbase + OFF_H + wid * HWARPSZ;
    const unsigned addrB = hwarp + (unsigned)((lane & 15) * HPITCH + (lane >> 4) * 16);
    const int gl = lane >> 2;
    const int tl = lane & 3;

    // ---- pin W fragments in registers (step-invariant) ----
    unsigned wa[8][3][4];
#pragma unroll
    for (int mt = 0; mt < 8; ++mt)
#pragma unroll
        for (int kc = 0; kc < 3; ++kc)
            ldsm_x4(wa[mt][kc][0], wa[mt][kc][1], wa[mt][kc][2], wa[mt][kc][3],
                    sbase + laneA + (unsigned)(mt * (16 * WPITCH * 2) + kc * 32));

    const float* xr = x + (size_t)(wb0 + lane) * (T_STEPS * NIN);  // lane<16 valid

    float xv[NIN];
    if (lane < NB) {
#pragma unroll
        for (int d = 0; d < NIN; ++d) xv[d] = xr[d];
    }

    float hreg[16], creg[16];
#pragma unroll
    for (int i = 0; i < 16; ++i) { hreg[i] = 0.0f; creg[i] = 0.0f; }

#pragma unroll 1
    for (int t = 0; t < T_STEPS; ++t) {
        // ---- write h (fp16) ----
#pragma unroll
        for (int p = 0; p < 2; ++p)
#pragma unroll
            for (int rr = 0; rr < 2; ++rr) {
                const int u = p * 16 + rr * 8 + gl;
                const int base = 8 * p + 4 * rr;
#pragma unroll
                for (int nt = 0; nt < 2; ++nt) {
                    unsigned v = pack_f16x2(hreg[base + 2 * nt + 1],
                                            hreg[base + 2 * nt]);
                    sts32(hwarp + (unsigned)(u * HPITCH + (nt * 8 + 2 * tl) * 2), v);
                }
            }
        // ---- write x rows: hi at 32..36, lo at 38..42 ----
        if (lane < NB) {
#pragma unroll
            for (int d = 0; d < NIN; ++d) {
                __half xh = __float2half(xv[d]);
                __half xl = __float2half(xv[d] - __half2float(xh));
                sts16(hwarp + (unsigned)((32 + d) * HPITCH + lane * 2),
                      *reinterpret_cast<unsigned short*>(&xh));
                sts16(hwarp + (unsigned)((38 + d) * HPITCH + lane * 2),
                      *reinterpret_cast<unsigned short*>(&xl));
            }
        }
        __syncwarp();

        // ---- prefetch next x ----
        if (t + 1 < T_STEPS && lane < NB) {
#pragma unroll
            for (int d = 0; d < NIN; ++d) xv[d] = xr[(t + 1) * NIN + d];
        }

        // ---- single-pass MMA from pinned registers ----
        float Cacc[8][2][4];
#pragma unroll
        for (int m = 0; m < 8; ++m)
#pragma unroll
            for (int n = 0; n < 2; ++n)
#pragma unroll
                for (int e = 0; e < 4; ++e) Cacc[m][n][e] = 0.0f;

#pragma unroll
        for (int kc = 0; kc < 3; ++kc) {
            unsigned rb0, rb1, rb2, rb3;
            ldsm_x4t(rb0, rb1, rb2, rb3, addrB + (unsigned)(kc * 16 * HPITCH));
#pragma unroll
            for (int mt = 0; mt < 8; ++mt) {
                MMA(Cacc[mt][0], wa[mt][kc][0], wa[mt][kc][1],
                    wa[mt][kc][2], wa[mt][kc][3], rb0, rb1);
                MMA(Cacc[mt][1], wa[mt][kc][0], wa[mt][kc][1],
                    wa[mt][kc][2], wa[mt][kc][3], rb2, rb3);
            }
        }

        // ---- activations (MUFU.TANH) + state update ----
#pragma unroll
        for (int p = 0; p < 2; ++p)
#pragma unroll
            for (int nt = 0; nt < 2; ++nt)
#pragma unroll
                for (int rr = 0; rr < 2; ++rr)
#pragma unroll
                    for (int e = 0; e < 2; ++e) {
                        const int j = rr * 2 + e;
                        const int idx = 8 * p + 4 * rr + 2 * nt + e;
                        float gi = sig_t(Cacc[p][nt][j]);
                        float gf = sig_t(Cacc[2 + p][nt][j]);
                        float gg = tanha(Cacc[4 + p][nt][j]);
                        float go = sig_t(Cacc[6 + p][nt][j]);
                        float cn = fmaf(gf, creg[idx], gi * gg);
                        creg[idx] = cn;
                        hreg[idx] = go * tanha(cn);
                    }
    }

    // ============ final projection ============
    float acc[4][2];
#pragma unroll
    for (int q = 0; q < 4; ++q) { acc[q][0] = 0.0f; acc[q][1] = 0.0f; }
#pragma unroll
    for (int p = 0; p < 2; ++p)
#pragma unroll
        for (int rr = 0; rr < 2; ++rr) {
            const int u = p * 16 + rr * 8 + gl;
            const float w0 = W_fc[u], w1 = W_fc[H + u];
#pragma unroll
            for (int nt = 0; nt < 2; ++nt)
#pragma unroll
                for (int e = 0; e < 2; ++e) {
                    const int idx = 8 * p + 4 * rr + 2 * nt + e;
                    acc[nt * 2 + e][0] = fmaf(hreg[idx], w0, acc[nt * 2 + e][0]);
                    acc[nt * 2 + e][1] = fmaf(hreg[idx], w1, acc[nt * 2 + e][1]);
                }
        }
#pragma unroll
    for (int off = 4; off <= 16; off <<= 1)
#pragma unroll
        for (int q = 0; q < 4; ++q) {
            acc[q][0] += __shfl_xor_sync(0xffffffffu, acc[q][0], off);
            acc[q][1] += __shfl_xor_sync(0xffffffffu, acc[q][1], off);
        }
    if (lane < 4) {
        const float f0 = b_fc[0], f1 = b_fc[1];
#pragma unroll
        for (int nt = 0; nt < 2; ++nt)
#pragma unroll
            for (int e = 0; e < 2; ++e) {
                const int col = nt * 8 + 2 * lane + e;
                out[(wb0 + col) * 2 + 0] = acc[nt * 2 + e][0] + f0;
                out[(wb0 + col) * 2 + 1] = acc[nt * 2 + e][1] + f1;
            }
    }
}

extern "C" void kernel_launch(void* const* d_in, const int* in_sizes, int n_in,
                              void* d_out, int out_size) {
    const float* x    = (const float*)d_in[0];
    const float* W_ih = (const float*)d_in[1];
    const float* W_hh = (const float*)d_in[2];
    const float* b_ih = (const float*)d_in[3];
    const float* b_hh = (const float*)d_in[4];
    const float* W_fc = (const float*)d_in[5];
    const float* b_fc = (const float*)d_in[6];
    float* out = (float*)d_out;

    int B = in_sizes[0] / (T_STEPS * NIN);
    int bpc = WARPS * NB;                      // 64 batches per CTA
    int blocks = (B + bpc - 1) / bpc;
    lstm_mma1p_kernel<<<blocks, THREADS>>>(x, W_ih, W_hh, b_ih, b_hh,
                                           W_fc, b_fc, out, B);
}

// round 8
// speedup vs baseline: 8.0302x; 1.0920x over previous
#include <cuda_runtime.h>
#include <cuda_fp16.h>

#define T_STEPS 200
#define NIN     5
#define H       32
#define G4      128          // 4H gate rows
#define NB      16           // batches per warp (2 n-tiles)
#define WARPS   4
#define THREADS (WARPS * 32)

#define WPITCH  56                        // halfs per W row (112 B, LDSM conflict-free)
#define WBYTES  (G4 * WPITCH * 2)         // 14336
#define OFF_H   WBYTES
#define HPITCH  48                        // bytes per Hbuf row
#define HWARPSZ (48 * HPITCH)             // 2304 per warp

struct SmemLayout {
    __half Whi[G4][WPITCH];
    __half Hbuf[WARPS][48][HPITCH / 2];
};

// ---------- PTX helpers ----------
__device__ __forceinline__ unsigned smem_u32(const void* p) {
    unsigned a;
    asm("{ .reg .u64 t; cvta.to.shared.u64 t, %1; cvt.u32.u64 %0, t; }"
        : "=r"(a) : "l"(p));
    return a;
}
__device__ __forceinline__ void ldsm_x4(unsigned& a0, unsigned& a1,
                                        unsigned& a2, unsigned& a3, unsigned addr) {
    asm volatile("ldmatrix.sync.aligned.m8n8.x4.shared.b16 {%0,%1,%2,%3}, [%4];"
                 : "=r"(a0), "=r"(a1), "=r"(a2), "=r"(a3) : "r"(addr));
}
__device__ __forceinline__ void ldsm_x4t(unsigned& b0, unsigned& b1,
                                         unsigned& b2, unsigned& b3, unsigned addr) {
    asm volatile("ldmatrix.sync.aligned.m8n8.x4.trans.shared.b16 {%0,%1,%2,%3}, [%4];"
                 : "=r"(b0), "=r"(b1), "=r"(b2), "=r"(b3) : "r"(addr));
}
#define MMA(Cr, A0, A1, A2, A3, B0, B1)                                        \
    asm volatile("mma.sync.aligned.m16n8k16.row.col.f32.f16.f16.f32 "          \
                 "{%0,%1,%2,%3}, {%4,%5,%6,%7}, {%8,%9}, {%0,%1,%2,%3};"       \
                 : "+f"((Cr)[0]), "+f"((Cr)[1]), "+f"((Cr)[2]), "+f"((Cr)[3])  \
                 : "r"(A0), "r"(A1), "r"(A2), "r"(A3), "r"(B0), "r"(B1))

__device__ __forceinline__ void sts32(unsigned addr, unsigned v) {
    asm volatile("st.shared.b32 [%0], %1;" :: "r"(addr), "r"(v) : "memory");
}
__device__ __forceinline__ void sts16(unsigned addr, unsigned short v) {
    asm volatile("st.shared.b16 [%0], %1;" :: "r"(addr), "h"(v) : "memory");
}

// ---------- packed f16x2 activation helpers ----------
__device__ __forceinline__ __half2 tanh2(__half2 v) {
    unsigned u = *reinterpret_cast<unsigned*>(&v), r;
    asm("tanh.approx.f16x2 %0, %1;" : "=r"(r) : "r"(u));
    return *reinterpret_cast<__half2*>(&r);
}
__device__ __forceinline__ __half2 pack2h(float e0, float e1) {   // low=e0
    unsigned r;
    asm("cvt.rn.f16x2.f32 %0, %1, %2;" : "=r"(r) : "f"(e1), "f"(e0));
    return *reinterpret_cast<__half2*>(&r);
}
__device__ __forceinline__ unsigned h2bits(__half2 v) {
    return *reinterpret_cast<unsigned*>(&v);
}

__global__ void __launch_bounds__(THREADS, 2)
lstm_pk_kernel(const float* __restrict__ x,
               const float* __restrict__ W_ih,
               const float* __restrict__ W_hh,
               const float* __restrict__ b_ih,
               const float* __restrict__ b_hh,
               const float* __restrict__ W_fc,
               const float* __restrict__ b_fc,
               float* __restrict__ out, int B) {
    __shared__ __align__(16) SmemLayout sm;

    const int tid  = threadIdx.x;
    const int wid  = tid >> 5;
    const int lane = tid & 31;

    // ============ init: W (fp16, x_lo duplicated cols) ============
    {
        const int g = tid;  // 0..127
        for (int k = 0; k < WPITCH; ++k) {
            float v;
            if (k < H)            v = W_hh[g * H + k];
            else if (k < 37)      v = W_ih[g * NIN + (k - 32)];
            else if (k == 37)     v = b_ih[g] + b_hh[g];
            else if (k >= 38 && k < 43) v = W_ih[g * NIN + (k - 38)]; // x_lo cols
            else                  v = 0.0f;
            sm.Whi[g][k] = __float2half(v);
        }
    }
    {   // zero H buffers
        unsigned* hz = (unsigned*)&sm.Hbuf[0][0][0];
        for (int i = tid; i < (WARPS * HWARPSZ) / 4; i += THREADS) hz[i] = 0u;
    }
    __syncthreads();
    if (tid < WARPS * NB)
        sm.Hbuf[tid / NB][37][tid % NB] = __float2half(1.0f);
    __syncthreads();

    const int wb0 = blockIdx.x * (WARPS * NB) + wid * NB;
    if (wb0 >= B) return;

    const unsigned sbase = smem_u32(&sm);
    const unsigned laneA = (unsigned)((lane & 15) * (WPITCH * 2) + (lane >> 4) * 16);
    const unsigned hwarp = sbase + OFF_H + wid * HWARPSZ;
    const unsigned addrB = hwarp + (unsigned)((lane & 15) * HPITCH + (lane >> 4) * 16);
    const int gl = lane >> 2;
    const int tl = lane & 3;

    // ---- pin W fragments in registers (step-invariant) ----
    unsigned wa[8][3][4];
#pragma unroll
    for (int mt = 0; mt < 8; ++mt)
#pragma unroll
        for (int kc = 0; kc < 3; ++kc)
            ldsm_x4(wa[mt][kc][0], wa[mt][kc][1], wa[mt][kc][2], wa[mt][kc][3],
                    sbase + laneA + (unsigned)(mt * (16 * WPITCH * 2) + kc * 32));

    const float* xr = x + (size_t)(wb0 + lane) * (T_STEPS * NIN);  // lane<16 valid

    float xv[NIN];
    if (lane < NB) {
#pragma unroll
        for (int d = 0; d < NIN; ++d) xv[d] = xr[d];
    }

    // state: c fp32 (16), h packed f16x2 (8): hidx = 4p + 2rr + nt, pair e0/e1
    float creg[16];
    __half2 h2[8];
#pragma unroll
    for (int i = 0; i < 16; ++i) creg[i] = 0.0f;
#pragma unroll
    for (int i = 0; i < 8; ++i) h2[i] = __half2(__ushort_as_half(0), __ushort_as_half(0));

    const __half2 half2_05 = __float2half2_rn(0.5f);

#pragma unroll 1
    for (int t = 0; t < T_STEPS; ++t) {
        // ---- write h (f16x2 pairs) ----
#pragma unroll
        for (int p = 0; p < 2; ++p)
#pragma unroll
            for (int rr = 0; rr < 2; ++rr) {
                const int u = p * 16 + rr * 8 + gl;
#pragma unroll
                for (int nt = 0; nt < 2; ++nt)
                    sts32(hwarp + (unsigned)(u * HPITCH + (nt * 8 + 2 * tl) * 2),
                          h2bits(h2[4 * p + 2 * rr + nt]));
            }
        // ---- write x rows: hi at 32..36, lo at 38..42 ----
        if (lane < NB) {
#pragma unroll
            for (int d = 0; d < NIN; ++d) {
                __half xh = __float2half(xv[d]);
                __half xl = __float2half(xv[d] - __half2float(xh));
                sts16(hwarp + (unsigned)((32 + d) * HPITCH + lane * 2),
                      *reinterpret_cast<unsigned short*>(&xh));
                sts16(hwarp + (unsigned)((38 + d) * HPITCH + lane * 2),
                      *reinterpret_cast<unsigned short*>(&xl));
            }
        }
        __syncwarp();

        // ---- prefetch next x ----
        if (t + 1 < T_STEPS && lane < NB) {
#pragma unroll
            for (int d = 0; d < NIN; ++d) xv[d] = xr[(t + 1) * NIN + d];
        }

        // ---- single-pass MMA from pinned registers ----
        float Cacc[8][2][4];
#pragma unroll
        for (int m = 0; m < 8; ++m)
#pragma unroll
            for (int n = 0; n < 2; ++n)
#pragma unroll
                for (int e = 0; e < 4; ++e) Cacc[m][n][e] = 0.0f;

#pragma unroll
        for (int kc = 0; kc < 3; ++kc) {
            unsigned rb0, rb1, rb2, rb3;
            ldsm_x4t(rb0, rb1, rb2, rb3, addrB + (unsigned)(kc * 16 * HPITCH));
#pragma unroll
            for (int mt = 0; mt < 8; ++mt) {
                MMA(Cacc[mt][0], wa[mt][kc][0], wa[mt][kc][1],
                    wa[mt][kc][2], wa[mt][kc][3], rb0, rb1);
                MMA(Cacc[mt][1], wa[mt][kc][0], wa[mt][kc][1],
                    wa[mt][kc][2], wa[mt][kc][3], rb2, rb3);
            }
        }

        // ---- packed f16x2 activations + fp32 c update ----
#pragma unroll
        for (int p = 0; p < 2; ++p)
#pragma unroll
            for (int nt = 0; nt < 2; ++nt)
#pragma unroll
                for (int rr = 0; rr < 2; ++rr) {
                    const int j0 = rr * 2, j1 = rr * 2 + 1;
                    __half2 ci = pack2h(Cacc[p][nt][j0],     Cacc[p][nt][j1]);
                    __half2 cf = pack2h(Cacc[2 + p][nt][j0], Cacc[2 + p][nt][j1]);
                    __half2 cg = pack2h(Cacc[4 + p][nt][j0], Cacc[4 + p][nt][j1]);
                    __half2 co = pack2h(Cacc[6 + p][nt][j0], Cacc[6 + p][nt][j1]);
                    __half2 gi = __hfma2(tanh2(__hmul2(ci, half2_05)), half2_05, half2_05);
                    __half2 gf = __hfma2(tanh2(__hmul2(cf, half2_05)), half2_05, half2_05);
                    __half2 gg = tanh2(cg);
                    __half2 go = __hfma2(tanh2(__hmul2(co, half2_05)), half2_05, half2_05);
                    __half2 ig = __hmul2(gi, gg);
                    const int idx = 8 * p + 4 * rr + 2 * nt;
                    float c0 = fmaf(__low2float(gf),  creg[idx],     __low2float(ig));
                    float c1 = fmaf(__high2float(gf), creg[idx + 1], __high2float(ig));
                    creg[idx]     = c0;
                    creg[idx + 1] = c1;
                    __half2 tc = tanh2(pack2h(c0, c1));
                    h2[4 * p + 2 * rr + nt] = __hmul2(go, tc);
                }
    }

    // ============ final projection ============
    float acc[4][2];
#pragma unroll
    for (int q = 0; q < 4; ++q) { acc[q][0] = 0.0f; acc[q][1] = 0.0f; }
#pragma unroll
    for (int p = 0; p < 2; ++p)
#pragma unroll
        for (int rr = 0; rr < 2; ++rr) {
            const int u = p * 16 + rr * 8 + gl;
            const float w0 = W_fc[u], w1 = W_fc[H + u];
#pragma unroll
            for (int nt = 0; nt < 2; ++nt) {
                const __half2 hv = h2[4 * p + 2 * rr + nt];
                const float hv0 = __low2float(hv), hv1 = __high2float(hv);
                acc[nt * 2 + 0][0] = fmaf(hv0, w0, acc[nt * 2 + 0][0]);
                acc[nt * 2 + 0][1] = fmaf(hv0, w1, acc[nt * 2 + 0][1]);
                acc[nt * 2 + 1][0] = fmaf(hv1, w0, acc[nt * 2 + 1][0]);
                acc[nt * 2 + 1][1] = fmaf(hv1, w1, acc[nt * 2 + 1][1]);
            }
        }
#pragma unroll
    for (int off = 4; off <= 16; off <<= 1)
#pragma unroll
        for (int q = 0; q < 4; ++q) {
            acc[q][0] += __shfl_xor_sync(0xffffffffu, acc[q][0], off);
            acc[q][1] += __shfl_xor_sync(0xffffffffu, acc[q][1], off);
        }
    if (lane < 4) {
        const float f0 = b_fc[0], f1 = b_fc[1];
#pragma unroll
        for (int nt = 0; nt < 2; ++nt)
#pragma unroll
            for (int e = 0; e < 2; ++e) {
                const int col = nt * 8 + 2 * lane + e;
                out[(wb0 + col) * 2 + 0] = acc[nt * 2 + e][0] + f0;
                out[(wb0 + col) * 2 + 1] = acc[nt * 2 + e][1] + f1;
            }
    }
}

extern "C" void kernel_launch(void* const* d_in, const int* in_sizes, int n_in,
                              void* d_out, int out_size) {
    const float* x    = (const float*)d_in[0];
    const float* W_ih = (const float*)d_in[1];
    const float* W_hh = (const float*)d_in[2];
    const float* b_ih = (const float*)d_in[3];
    const float* b_hh = (const float*)d_in[4];
    const float* W_fc = (const float*)d_in[5];
    const float* b_fc = (const float*)d_in[6];
    float* out = (float*)d_out;

    int B = in_sizes[0] / (T_STEPS * NIN);
    int bpc = WARPS * NB;                      // 64 batches per CTA
    int blocks = (B + bpc - 1) / bpc;
    lstm_pk_kernel<<<blocks, THREADS>>>(x, W_ih, W_hh, b_ih, b_hh,
                                        W_fc, b_fc, out, B);
}